// round 12
// baseline (speedup 1.0000x reference)
#include <cuda_runtime.h>
#include <math.h>

#define H      2048
#define TSTEPS 1024
#define NCTA   294               // 2 CTAs per SM, 7 columns each
#define MAXC   7
#define JPAD   (NCTA * MAXC)     // 2058 padded columns
#define HPAD   2060
#define HREP   8                 // h replicas (consumers read cta&7)
#define HRS    2176              // replica stride in floats
#define NTH    224               // 7 warps, 1 column each
#define NWARP  7

// smem layout (floats): r cols [0,7H) ; z cols 0..5 [7H,13H) ; hbuf [13H,14H) ; flag,cnt
#define ZS_BASE   (7 * H)
#define HBUF_OFF  (13 * H)
#define CTRL_OFF  (14 * H)               // [0]=flag, [1]=cnt
#define SMEM_BYTES ((14 * H + 16) * 4)   // 114,752 B -> 2 CTAs = 229,504 <= 233,472

typedef unsigned long long u64;

#define FFMA2(acc, a, b) \
    asm("fma.rn.f32x2 %0, %1, %2, %0;" : "+l"(acc) : "l"(a), "l"(b))

__device__ __forceinline__ float2 unpk(u64 v) {
    float2 r;
    asm("mov.b64 {%0, %1}, %2;" : "=f"(r.x), "=f"(r.y) : "l"(v));
    return r;
}

// ---------------- persistent device state ----------------
__device__ float    g_Wt[3][(size_t)JPAD * H];  // transposed: g_Wt[g][j][k] = Wh_g[k][j]
__device__ float    g_u[3][HPAD];
__device__ float    g_v[3][HPAD];
__device__ float    g_xs[TSTEPS];
__device__ float    g_hrep[2][HREP][HRS];       // replicated double-buffered h
__device__ unsigned g_ctr;

// ---------------- memory-order helpers ----------------
__device__ __forceinline__ unsigned ld_relax_g(const unsigned* p) {
    unsigned v;
    asm volatile("ld.relaxed.gpu.global.b32 %0, [%1];" : "=r"(v) : "l"(p) : "memory");
    return v;
}
__device__ __forceinline__ unsigned ld_acq_g(const unsigned* p) {
    unsigned v;
    asm volatile("ld.acquire.gpu.global.b32 %0, [%1];" : "=r"(v) : "l"(p) : "memory");
    return v;
}
__device__ __forceinline__ void red_rel_add_g(unsigned* p, unsigned v) {
    asm volatile("red.release.gpu.global.add.u32 [%0], %1;" :: "l"(p), "r"(v) : "memory");
}
__device__ __forceinline__ unsigned ld_acq_s(unsigned saddr) {
    unsigned v;
    asm volatile("ld.acquire.cta.shared.u32 %0, [%1];" : "=r"(v) : "r"(saddr) : "memory");
    return v;
}
__device__ __forceinline__ void st_rel_s(unsigned saddr, unsigned v) {
    asm volatile("st.release.cta.shared.u32 [%0], %1;" :: "r"(saddr), "r"(v) : "memory");
}
__device__ __forceinline__ unsigned atom_acqrel_add_s(unsigned saddr, unsigned v) {
    unsigned old;
    asm volatile("atom.acq_rel.cta.shared.add.u32 %0, [%1], %2;"
                 : "=r"(old) : "r"(saddr), "r"(v) : "memory");
    return old;
}

// ---------------- init ----------------
__global__ void init_kernel(const float* __restrict__ x) {
    int t = threadIdx.x;              // 0..1023
    int row = t >> 5;
    int c = t & 31;
    int oc = (row & 1) ? (31 - c) : c;
    g_xs[t] = x[(row << 5) + oc];
    for (int i = t; i < 2 * HREP * HRS; i += 1024)
        ((float*)g_hrep)[i] = 0.0f;
    for (int i = t; i < 3 * HPAD; i += 1024) {
        ((float*)g_u)[i] = 0.0f;
        ((float*)g_v)[i] = 0.0f;
    }
    if (t == 0) g_ctr = 0u;
}

// ---------------- transpose Whr/Whz/Whn into g_Wt (column-major) ----------------
__global__ void transpose_kernel(const float* __restrict__ Whr,
                                 const float* __restrict__ Whz,
                                 const float* __restrict__ Whn) {
    __shared__ float tile[32][33];
    const float* src = (blockIdx.z == 0) ? Whr : (blockIdx.z == 1) ? Whz : Whn;
    float* dst = g_Wt[blockIdx.z];
    int k0 = blockIdx.x * 32;
    int j0 = blockIdx.y * 32;
    #pragma unroll
    for (int i = 0; i < 32; i += 8)
        tile[threadIdx.y + i][threadIdx.x] =
            src[(size_t)(k0 + threadIdx.y + i) * H + j0 + threadIdx.x];
    __syncthreads();
    #pragma unroll
    for (int i = 0; i < 32; i += 8)
        dst[(size_t)(j0 + threadIdx.y + i) * H + k0 + threadIdx.x] =
            tile[threadIdx.x][threadIdx.y + i];
}

// ---------------- prep ----------------
__global__ void prep_kernel(const float* __restrict__ We, const float* __restrict__ be,
                            const float* __restrict__ Wir, const float* __restrict__ bir,
                            const float* __restrict__ Wiz, const float* __restrict__ biz,
                            const float* __restrict__ Win, const float* __restrict__ bin_) {
    int j  = blockIdx.x * 128 + threadIdx.x;
    int k0 = blockIdx.y * 128;
    float u0 = 0, v0 = 0, u1 = 0, v1 = 0, u2 = 0, v2 = 0;
    for (int k = k0; k < k0 + 128; k++) {
        float we = We[k];
        float b  = be[k];
        float w;
        w = Wir[(size_t)k * H + j]; u0 = fmaf(we, w, u0); v0 = fmaf(b, w, v0);
        w = Wiz[(size_t)k * H + j]; u1 = fmaf(we, w, u1); v1 = fmaf(b, w, v1);
        w = Win[(size_t)k * H + j]; u2 = fmaf(we, w, u2); v2 = fmaf(b, w, v2);
    }
    if (blockIdx.y == 0) { v0 += bir[j]; v1 += biz[j]; v2 += bin_[j]; }
    atomicAdd(&g_u[0][j], u0); atomicAdd(&g_v[0][j], v0);
    atomicAdd(&g_u[1][j], u1); atomicAdd(&g_v[1][j], v1);
    atomicAdd(&g_u[2][j], u2); atomicAdd(&g_v[2][j], v2);
}

// ---------------- persistent recurrent kernel (occupancy 2) ----------------
extern __shared__ float sw[];

__global__ void __launch_bounds__(NTH, 2) gru_kernel(const float* __restrict__ bhn,
                                                     float* __restrict__ out) {
    const int cta  = blockIdx.x;
    const int tid  = threadIdx.x;
    const int warp = tid >> 5;
    const int lane = tid & 31;
    const int cb   = cta * MAXC;
    const int rep  = cta & (HREP - 1);

    unsigned* ctrl = (unsigned*)(sw + CTRL_OFF);
    const unsigned flag_sa = (unsigned)__cvta_generic_to_shared(&ctrl[0]);
    const unsigned cnt_sa  = (unsigned)__cvta_generic_to_shared(&ctrl[1]);
    if (tid == 0) { ctrl[0] = 0u; ctrl[1] = 0u; }

    // ---- preload weights: r cols 0..6, z cols 0..5 into SMEM ----
    {
        const float4* s0 = (const float4*)(g_Wt[0] + (size_t)cb * H);   // 7 r cols
        const float4* s1 = (const float4*)(g_Wt[1] + (size_t)cb * H);   // 6 z cols
        float4* d0 = (float4*)sw;
        float4* d1 = (float4*)(sw + ZS_BASE);
        const int n4r = 7 * H / 4;
        const int n4z = 6 * H / 4;
        for (int i = tid; i < n4r; i += NTH) d0[i] = s0[i];
        for (int i = tid; i < n4z; i += NTH) d1[i] = s1[i];
    }

    // ---- this warp's 1 column ----
    const int j0 = cb + warp;

    // ---- Whn column resident in registers (constant across steps) ----
    ulonglong2 wn[16];
    {
        const ulonglong2* p0 = (const ulonglong2*)(g_Wt[2] + (size_t)j0 * H);
        #pragma unroll
        for (int i = 0; i < 16; i++) wn[i] = p0[lane + 32 * i];
    }

    // ---- epilogue constants on lane 0 ----
    float ur = 0, vr = 0, uz = 0, vz = 0, un = 0, vn = 0, bh = 0, hprev = 0.0f;
    if (lane == 0) {
        int js = (j0 < H) ? j0 : (H - 1);
        ur = g_u[0][js]; vr = g_v[0][js];
        uz = g_u[1][js]; vz = g_v[1][js];
        un = g_u[2][js]; vn = g_v[2][js];
        bh = bhn[js];
    }

    const ulonglong2* sr = (const ulonglong2*)(sw + (size_t)warp * H);
    const ulonglong2* sz = (const ulonglong2*)(sw + (size_t)(ZS_BASE + warp * H)); // warp6: unused
    const ulonglong2* gz = (const ulonglong2*)(g_Wt[1] + (size_t)(cb + 6) * H);    // warp6's z col
    const ulonglong2* hb = (const ulonglong2*)(sw + HBUF_OFF);
    const int rotA = (cta * 5) & 255;   // stagger line sweep across CTAs
    __syncthreads();   // smem weights + ctrl ready

    for (int t = 1; t <= TSTEPS; t++) {
        const int rb = (t - 1) & 1;
        const int wb = t & 1;

        float xt = __ldg(&g_xs[t - 1]);   // barrier-independent

        // ---- warp6: prefetch chunk0 of streamed z col (step-invariant) BEFORE spin ----
        ulonglong2 dpre[4];
        if (warp == 6) {
            #pragma unroll
            for (int i = 0; i < 4; i++) dpre[i] = __ldcg(gz + lane + 32 * i);
        }

        // ---- barrier: warp0 lane0 polls global counter, publishes smem flag ----
        if (warp == 0 && lane == 0) {
            if (t > 1) {
                const unsigned tgt = (unsigned)(t - 1) * NCTA;
                while (ld_relax_g(&g_ctr) < tgt) { }
                (void)ld_acq_g(&g_ctr);    // ordering edge (gpu scope)
            }
            st_rel_s(flag_sa, (unsigned)t);
        }
        while (ld_acq_s(flag_sa) < (unsigned)t) { }

        // ---- phase A: fill h[0:1024] -> smem (rotated sweep); phase B into regs ----
        const float4* hsrc = (const float4*)g_hrep[rb][rep];
        float4* hdst = (float4*)(sw + HBUF_OFF);
        {
            #pragma unroll
            for (int i = tid; i < 256; i += NTH) {
                int s = (i + rotA) & 255;
                hdst[s] = __ldcg(hsrc + s);
            }
        }
        float4 bA = __ldcg(hsrc + 256 + tid);                       // 256..479
        float4 bB;
        if (tid < 32) bB = __ldcg(hsrc + 480 + tid);                // 480..511
        __syncthreads();   // phase A visible

        // ---- dot iters 0..7 on phase A (phase-B LDGs in flight) ----
        u64 ar = 0, az = 0, an = 0;
        if (warp < 6) {
            #pragma unroll
            for (int i = 0; i < 8; i++) {
                ulonglong2 h = hb[lane + 32 * i];
                u64 hA = h.x, hB = h.y;
                ulonglong2 a = sr[lane + 32 * i];
                ulonglong2 c = sz[lane + 32 * i];
                FFMA2(ar, hA, a.x); FFMA2(ar, hB, a.y);
                FFMA2(az, hA, c.x); FFMA2(az, hB, c.y);
                FFMA2(an, hA, wn[i].x); FFMA2(an, hB, wn[i].y);
            }
        } else {
            #pragma unroll
            for (int c = 0; c < 2; c++) {
                ulonglong2 dcur[4];
                #pragma unroll
                for (int i = 0; i < 4; i++) dcur[i] = dpre[i];
                #pragma unroll
                for (int i = 0; i < 4; i++)
                    dpre[i] = __ldcg(gz + lane + 32 * (4 * (c + 1) + i));
                #pragma unroll
                for (int i = 0; i < 4; i++) {
                    int it = 4 * c + i;
                    ulonglong2 h = hb[lane + 32 * it];
                    u64 hA = h.x, hB = h.y;
                    ulonglong2 a = sr[lane + 32 * it];
                    ulonglong2 d = dcur[i];
                    FFMA2(ar, hA, a.x); FFMA2(ar, hB, a.y);
                    FFMA2(az, hA, d.x); FFMA2(az, hB, d.y);
                    FFMA2(an, hA, wn[it].x); FFMA2(an, hB, wn[it].y);
                }
            }
        }

        // ---- land phase B in smem ----
        hdst[256 + tid] = bA;
        if (tid < 32) hdst[480 + tid] = bB;
        __syncthreads();   // phase B visible

        // ---- dot iters 8..15 on phase B ----
        if (warp < 6) {
            #pragma unroll
            for (int i = 8; i < 16; i++) {
                ulonglong2 h = hb[lane + 32 * i];
                u64 hA = h.x, hB = h.y;
                ulonglong2 a = sr[lane + 32 * i];
                ulonglong2 c = sz[lane + 32 * i];
                FFMA2(ar, hA, a.x); FFMA2(ar, hB, a.y);
                FFMA2(az, hA, c.x); FFMA2(az, hB, c.y);
                FFMA2(an, hA, wn[i].x); FFMA2(an, hB, wn[i].y);
            }
        } else {
            #pragma unroll
            for (int c = 2; c < 4; c++) {
                ulonglong2 dcur[4];
                #pragma unroll
                for (int i = 0; i < 4; i++) dcur[i] = dpre[i];
                if (c < 3) {
                    #pragma unroll
                    for (int i = 0; i < 4; i++)
                        dpre[i] = __ldcg(gz + lane + 32 * (4 * (c + 1) + i));
                }
                #pragma unroll
                for (int i = 0; i < 4; i++) {
                    int it = 4 * c + i;
                    ulonglong2 h = hb[lane + 32 * it];
                    u64 hA = h.x, hB = h.y;
                    ulonglong2 a = sr[lane + 32 * it];
                    ulonglong2 d = dcur[i];
                    FFMA2(ar, hA, a.x); FFMA2(ar, hB, a.y);
                    FFMA2(az, hA, d.x); FFMA2(az, hB, d.y);
                    FFMA2(an, hA, wn[it].x); FFMA2(an, hB, wn[it].y);
                }
            }
        }

        // ---- collapse pairs; reduce r/z first so sigmoid starts early ----
        float2 pr = unpk(ar), pz = unpk(az);
        float Ar = pr.x + pr.y, Az = pz.x + pz.y;
        #pragma unroll
        for (int s = 16; s > 0; s >>= 1) {
            Ar += __shfl_xor_sync(0xffffffffu, Ar, s);
            Az += __shfl_xor_sync(0xffffffffu, Az, s);
        }
        float arv = fmaf(xt, ur, vr) + Ar;
        float azv = fmaf(xt, uz, vz) + Az;
        float r = __fdividef(1.0f, 1.0f + __expf(-arv));
        float z = __fdividef(1.0f, 1.0f + __expf(-azv));

        float2 pn = unpk(an);
        float An = pn.x + pn.y;
        #pragma unroll
        for (int s = 16; s > 0; s >>= 1)
            An += __shfl_xor_sync(0xffffffffu, An, s);

        if (lane == 0) {
            float anv = fmaf(xt, un, vn);
            float v = anv + r * (An + bh);
            float n = 1.0f - __fdividef(2.0f, 1.0f + __expf(2.0f * v));  // tanh(v)
            float hn = (1.0f - z) * n + z * hprev;
            hprev = hn;
            if (j0 < H) {
                #pragma unroll
                for (int rr = 0; rr < HREP; rr++)
                    __stcg(&g_hrep[wb][rr][j0], hn);
                if (t == TSTEPS) out[j0] = hn;
            }
            // ---- publish: per-warp cta-release arrival; winner does gpu release ----
            unsigned old = atom_acqrel_add_s(cnt_sa, 1u);
            if (old == (unsigned)(NWARP * t - 1)) red_rel_add_g(&g_ctr, 1u);
        }
    }
}

// ---------------- host launch ----------------
extern "C" void kernel_launch(void* const* d_in, const int* in_sizes, int n_in,
                              void* d_out, int out_size) {
    const float* x    = (const float*)d_in[0];
    const float* We   = (const float*)d_in[1];
    const float* be   = (const float*)d_in[2];
    const float* Wir  = (const float*)d_in[3];
    const float* bir  = (const float*)d_in[4];
    const float* Wiz  = (const float*)d_in[5];
    const float* biz  = (const float*)d_in[6];
    const float* Win  = (const float*)d_in[7];
    const float* bin_ = (const float*)d_in[8];
    const float* Whr  = (const float*)d_in[9];
    const float* Whz  = (const float*)d_in[10];
    const float* Whn  = (const float*)d_in[11];
    const float* bhn  = (const float*)d_in[12];
    float* out = (float*)d_out;

    cudaFuncSetAttribute(gru_kernel, cudaFuncAttributeMaxDynamicSharedMemorySize,
                         SMEM_BYTES);

    init_kernel<<<1, 1024>>>(x);
    transpose_kernel<<<dim3(H / 32, H / 32, 3), dim3(32, 8)>>>(Whr, Whz, Whn);
    prep_kernel<<<dim3(H / 128, H / 128), 128>>>(We, be, Wir, bir, Wiz, biz, Win, bin_);
    gru_kernel<<<NCTA, NTH, SMEM_BYTES>>>(bhn, out);
}

// round 13
// speedup vs baseline: 1.2638x; 1.2638x over previous
#include <cuda_runtime.h>
#include <math.h>

#define H      2048
#define TSTEPS 1024
#define NCTA   147
#define MAXC   14
#define JPAD   (NCTA * MAXC)      // 2058 padded columns
#define HPAD   2060
#define HREP   16                 // h replicas (consumers read cta&15)
#define HRS    2176               // replica stride in floats (16B aligned)
#define NTH    224                // 7 warps, 2 columns each
#define NWARP  7

// smem layout (floats): r cols [0,14H) ; z cols 0..12 [14H,27H) ; hbuf [27H,28H) ; flag,cnt
#define ZS_BASE   (14 * H)
#define HBUF_OFF  (27 * H)
#define CTRL_OFF  (28 * H)               // [0]=flag, [1]=cnt
#define SMEM_BYTES ((28 * H + 16) * 4)   // 229,440 B

typedef unsigned long long u64;

#define FFMA2(acc, a, b) \
    asm("fma.rn.f32x2 %0, %1, %2, %0;" : "+l"(acc) : "l"(a), "l"(b))

__device__ __forceinline__ float2 unpk(u64 v) {
    float2 r;
    asm("mov.b64 {%0, %1}, %2;" : "=f"(r.x), "=f"(r.y) : "l"(v));
    return r;
}

// ---------------- persistent device state ----------------
__device__ float    g_Wt[3][(size_t)JPAD * H];  // transposed: g_Wt[g][j][k] = Wh_g[k][j]
__device__ float    g_u[3][HPAD];
__device__ float    g_v[3][HPAD];
__device__ float    g_xs[TSTEPS];
__device__ float    g_hrep[2][HREP][HRS];       // replicated double-buffered h
__device__ unsigned g_ctr;

// ---------------- memory-order helpers ----------------
__device__ __forceinline__ unsigned ld_relax_g(const unsigned* p) {
    unsigned v;
    asm volatile("ld.relaxed.gpu.global.b32 %0, [%1];" : "=r"(v) : "l"(p) : "memory");
    return v;
}
__device__ __forceinline__ unsigned ld_acq_g(const unsigned* p) {
    unsigned v;
    asm volatile("ld.acquire.gpu.global.b32 %0, [%1];" : "=r"(v) : "l"(p) : "memory");
    return v;
}
__device__ __forceinline__ unsigned atom_acqrel_add_g(unsigned* p, unsigned v) {
    unsigned old;
    asm volatile("atom.acq_rel.gpu.global.add.u32 %0, [%1], %2;"
                 : "=r"(old) : "l"(p), "r"(v) : "memory");
    return old;
}
__device__ __forceinline__ unsigned ld_acq_s(unsigned saddr) {
    unsigned v;
    asm volatile("ld.acquire.cta.shared.u32 %0, [%1];" : "=r"(v) : "r"(saddr) : "memory");
    return v;
}
__device__ __forceinline__ void st_rel_s(unsigned saddr, unsigned v) {
    asm volatile("st.release.cta.shared.u32 [%0], %1;" :: "r"(saddr), "r"(v) : "memory");
}
__device__ __forceinline__ unsigned atom_acqrel_add_s(unsigned saddr, unsigned v) {
    unsigned old;
    asm volatile("atom.acq_rel.cta.shared.add.u32 %0, [%1], %2;"
                 : "=r"(old) : "r"(saddr), "r"(v) : "memory");
    return old;
}

// ---------------- init ----------------
__global__ void init_kernel(const float* __restrict__ x) {
    int t = threadIdx.x;              // 0..1023
    int row = t >> 5;
    int c = t & 31;
    int oc = (row & 1) ? (31 - c) : c;
    g_xs[t] = x[(row << 5) + oc];
    for (int i = t; i < 2 * HREP * HRS; i += 1024)
        ((float*)g_hrep)[i] = 0.0f;
    for (int i = t; i < 3 * HPAD; i += 1024) {
        ((float*)g_u)[i] = 0.0f;
        ((float*)g_v)[i] = 0.0f;
    }
    if (t == 0) g_ctr = 0u;
}

// ---------------- transpose Whr/Whz/Whn into g_Wt (column-major) ----------------
__global__ void transpose_kernel(const float* __restrict__ Whr,
                                 const float* __restrict__ Whz,
                                 const float* __restrict__ Whn) {
    __shared__ float tile[32][33];
    const float* src = (blockIdx.z == 0) ? Whr : (blockIdx.z == 1) ? Whz : Whn;
    float* dst = g_Wt[blockIdx.z];
    int k0 = blockIdx.x * 32;
    int j0 = blockIdx.y * 32;
    #pragma unroll
    for (int i = 0; i < 32; i += 8)
        tile[threadIdx.y + i][threadIdx.x] =
            src[(size_t)(k0 + threadIdx.y + i) * H + j0 + threadIdx.x];
    __syncthreads();
    #pragma unroll
    for (int i = 0; i < 32; i += 8)
        dst[(size_t)(j0 + threadIdx.y + i) * H + k0 + threadIdx.x] =
            tile[threadIdx.x][threadIdx.y + i];
}

// ---------------- prep ----------------
__global__ void prep_kernel(const float* __restrict__ We, const float* __restrict__ be,
                            const float* __restrict__ Wir, const float* __restrict__ bir,
                            const float* __restrict__ Wiz, const float* __restrict__ biz,
                            const float* __restrict__ Win, const float* __restrict__ bin_) {
    int j  = blockIdx.x * 128 + threadIdx.x;
    int k0 = blockIdx.y * 128;
    float u0 = 0, v0 = 0, u1 = 0, v1 = 0, u2 = 0, v2 = 0;
    for (int k = k0; k < k0 + 128; k++) {
        float we = We[k];
        float b  = be[k];
        float w;
        w = Wir[(size_t)k * H + j]; u0 = fmaf(we, w, u0); v0 = fmaf(b, w, v0);
        w = Wiz[(size_t)k * H + j]; u1 = fmaf(we, w, u1); v1 = fmaf(b, w, v1);
        w = Win[(size_t)k * H + j]; u2 = fmaf(we, w, u2); v2 = fmaf(b, w, v2);
    }
    if (blockIdx.y == 0) { v0 += bir[j]; v1 += biz[j]; v2 += bin_[j]; }
    atomicAdd(&g_u[0][j], u0); atomicAdd(&g_v[0][j], v0);
    atomicAdd(&g_u[1][j], u1); atomicAdd(&g_v[1][j], v1);
    atomicAdd(&g_u[2][j], u2); atomicAdd(&g_v[2][j], v2);
}

// ---------------- persistent recurrent kernel ----------------
extern __shared__ float sw[];

__global__ void __launch_bounds__(NTH, 1) gru_kernel(const float* __restrict__ bhn,
                                                     float* __restrict__ out) {
    const int cta  = blockIdx.x;
    const int tid  = threadIdx.x;
    const int warp = tid >> 5;
    const int lane = tid & 31;
    const int cb   = cta * MAXC;
    const int rep  = cta & (HREP - 1);

    unsigned* ctrl = (unsigned*)(sw + CTRL_OFF);
    const unsigned flag_sa = (unsigned)__cvta_generic_to_shared(&ctrl[0]);
    const unsigned cnt_sa  = (unsigned)__cvta_generic_to_shared(&ctrl[1]);
    if (tid == 0) { ctrl[0] = 0u; ctrl[1] = 0u; }

    // ---- preload weights: r cols 0..13, z cols 0..12 into SMEM ----
    {
        const float4* s0 = (const float4*)(g_Wt[0] + (size_t)cb * H);   // 14 r cols
        const float4* s1 = (const float4*)(g_Wt[1] + (size_t)cb * H);   // 13 z cols
        float4* d0 = (float4*)sw;
        float4* d1 = (float4*)(sw + ZS_BASE);
        const int n4r = 14 * H / 4;
        const int n4z = 13 * H / 4;
        for (int i = tid; i < n4r; i += NTH) d0[i] = s0[i];
        for (int i = tid; i < n4z; i += NTH) d1[i] = s1[i];
    }

    // ---- this warp's 2 columns ----
    const int c0 = 2 * warp, c1 = c0 + 1;
    const int j0 = cb + c0, j1 = cb + c1;

    // ---- Whn columns resident in registers (constant across steps) ----
    ulonglong2 wn0[16], wn1[16];
    {
        const ulonglong2* p0 = (const ulonglong2*)(g_Wt[2] + (size_t)j0 * H);
        const ulonglong2* p1 = (const ulonglong2*)(g_Wt[2] + (size_t)j1 * H);
        #pragma unroll
        for (int i = 0; i < 16; i++) { wn0[i] = p0[lane + 32 * i]; wn1[i] = p1[lane + 32 * i]; }
    }

    // ---- epilogue constants on lanes 0,1 ----
    const int jj = (lane == 0) ? j0 : j1;
    float ur = 0, vr = 0, uz = 0, vz = 0, un = 0, vn = 0, bh = 0, hprev = 0.0f;
    if (lane < 2) {
        int js = (jj < H) ? jj : (H - 1);
        ur = g_u[0][js]; vr = g_v[0][js];
        uz = g_u[1][js]; vz = g_v[1][js];
        un = g_u[2][js]; vn = g_v[2][js];
        bh = bhn[js];
    }

    const ulonglong2* sr0 = (const ulonglong2*)(sw + (size_t)c0 * H);
    const ulonglong2* sr1 = (const ulonglong2*)(sw + (size_t)c1 * H);
    const ulonglong2* sz0 = (const ulonglong2*)(sw + (size_t)(ZS_BASE + c0 * H));
    const ulonglong2* sz1 = (const ulonglong2*)(sw + (size_t)(ZS_BASE + c1 * H)); // warp6: unused
    const ulonglong2* gz1 = (const ulonglong2*)(g_Wt[1] + (size_t)(cb + 13) * H); // warp6's z col
    const ulonglong2* hb  = (const ulonglong2*)(sw + HBUF_OFF);
    const int rotA = (cta * 5) & 255;   // stagger line sweep across CTAs
    __syncthreads();   // smem weights + ctrl ready

    for (int t = 1; t <= TSTEPS; t++) {
        const int rb = (t - 1) & 1;
        const int wb = t & 1;

        float xt = __ldg(&g_xs[t - 1]);   // barrier-independent

        // ---- warp6: prefetch chunk0 of streamed z col (step-invariant) BEFORE spin ----
        ulonglong2 dpre[4];
        if (warp == 6) {
            #pragma unroll
            for (int i = 0; i < 4; i++) dpre[i] = __ldcg(gz1 + lane + 32 * i);
        }

        // ---- barrier: warp0 lane0 polls global counter unless this CTA was the
        //      global laggard last step (then flag_sa was pre-released) ----
        if (warp == 0 && lane == 0) {
            if (t > 1) {
                if (ld_acq_s(flag_sa) < (unsigned)t) {
                    const unsigned tgt = (unsigned)(t - 1) * NCTA;
                    unsigned v = ld_relax_g(&g_ctr);
                    while (v < tgt) {
                        unsigned v2 = ld_relax_g(&g_ctr);
                        unsigned v3 = ld_relax_g(&g_ctr);
                        v = (v2 > v3) ? v2 : v3;
                    }
                    (void)ld_acq_g(&g_ctr);    // ordering edge (gpu scope)
                    st_rel_s(flag_sa, (unsigned)t);
                }
            } else {
                st_rel_s(flag_sa, 1u);
            }
        }
        while (ld_acq_s(flag_sa) < (unsigned)t) { }

        // ---- phase A: fill h[0:1024] -> smem (rotated sweep); phase B into regs ----
        const float4* hsrc = (const float4*)g_hrep[rb][rep];
        float4* hdst = (float4*)(sw + HBUF_OFF);
        {
            #pragma unroll
            for (int i = tid; i < 256; i += NTH) {
                int s = (i + rotA) & 255;
                hdst[s] = __ldcg(hsrc + s);
            }
        }
        float4 bA = __ldcg(hsrc + 256 + tid);                       // 256..479
        float4 bB;
        if (tid < 32) bB = __ldcg(hsrc + 480 + tid);                // 480..511
        __syncthreads();   // phase A visible

        // ---- dot iters 0..7 on phase A (phase-B LDGs in flight) ----
        u64 ar0 = 0, ar1 = 0, az0 = 0, az1 = 0, an0 = 0, an1 = 0;
        if (warp < 6) {
            #pragma unroll
            for (int i = 0; i < 8; i++) {
                ulonglong2 h = hb[lane + 32 * i];
                u64 hA = h.x, hB = h.y;
                ulonglong2 a = sr0[lane + 32 * i];
                ulonglong2 b = sr1[lane + 32 * i];
                ulonglong2 c = sz0[lane + 32 * i];
                ulonglong2 d = sz1[lane + 32 * i];
                FFMA2(ar0, hA, a.x); FFMA2(ar0, hB, a.y);
                FFMA2(ar1, hA, b.x); FFMA2(ar1, hB, b.y);
                FFMA2(az0, hA, c.x); FFMA2(az0, hB, c.y);
                FFMA2(az1, hA, d.x); FFMA2(az1, hB, d.y);
                FFMA2(an0, hA, wn0[i].x); FFMA2(an0, hB, wn0[i].y);
                FFMA2(an1, hA, wn1[i].x); FFMA2(an1, hB, wn1[i].y);
            }
        } else {
            #pragma unroll
            for (int c = 0; c < 2; c++) {
                ulonglong2 dcur[4];
                #pragma unroll
                for (int i = 0; i < 4; i++) dcur[i] = dpre[i];
                #pragma unroll
                for (int i = 0; i < 4; i++)
                    dpre[i] = __ldcg(gz1 + lane + 32 * (4 * (c + 1) + i));
                #pragma unroll
                for (int i = 0; i < 4; i++) {
                    int it = 4 * c + i;
                    ulonglong2 h = hb[lane + 32 * it];
                    u64 hA = h.x, hB = h.y;
                    ulonglong2 a = sr0[lane + 32 * it];
                    ulonglong2 b = sr1[lane + 32 * it];
                    ulonglong2 cc = sz0[lane + 32 * it];
                    ulonglong2 d = dcur[i];
                    FFMA2(ar0, hA, a.x); FFMA2(ar0, hB, a.y);
                    FFMA2(ar1, hA, b.x); FFMA2(ar1, hB, b.y);
                    FFMA2(az0, hA, cc.x); FFMA2(az0, hB, cc.y);
                    FFMA2(az1, hA, d.x); FFMA2(az1, hB, d.y);
                    FFMA2(an0, hA, wn0[it].x); FFMA2(an0, hB, wn0[it].y);
                    FFMA2(an1, hA, wn1[it].x); FFMA2(an1, hB, wn1[it].y);
                }
            }
        }

        // ---- land phase B in smem ----
        hdst[256 + tid] = bA;
        if (tid < 32) hdst[480 + tid] = bB;
        __syncthreads();   // phase B visible

        // ---- dot iters 8..15 on phase B ----
        if (warp < 6) {
            #pragma unroll
            for (int i = 8; i < 16; i++) {
                ulonglong2 h = hb[lane + 32 * i];
                u64 hA = h.x, hB = h.y;
                ulonglong2 a = sr0[lane + 32 * i];
                ulonglong2 b = sr1[lane + 32 * i];
                ulonglong2 c = sz0[lane + 32 * i];
                ulonglong2 d = sz1[lane + 32 * i];
                FFMA2(ar0, hA, a.x); FFMA2(ar0, hB, a.y);
                FFMA2(ar1, hA, b.x); FFMA2(ar1, hB, b.y);
                FFMA2(az0, hA, c.x); FFMA2(az0, hB, c.y);
                FFMA2(az1, hA, d.x); FFMA2(az1, hB, d.y);
                FFMA2(an0, hA, wn0[i].x); FFMA2(an0, hB, wn0[i].y);
                FFMA2(an1, hA, wn1[i].x); FFMA2(an1, hB, wn1[i].y);
            }
        } else {
            #pragma unroll
            for (int c = 2; c < 4; c++) {
                ulonglong2 dcur[4];
                #pragma unroll
                for (int i = 0; i < 4; i++) dcur[i] = dpre[i];
                if (c < 3) {
                    #pragma unroll
                    for (int i = 0; i < 4; i++)
                        dpre[i] = __ldcg(gz1 + lane + 32 * (4 * (c + 1) + i));
                }
                #pragma unroll
                for (int i = 0; i < 4; i++) {
                    int it = 4 * c + i;
                    ulonglong2 h = hb[lane + 32 * it];
                    u64 hA = h.x, hB = h.y;
                    ulonglong2 a = sr0[lane + 32 * it];
                    ulonglong2 b = sr1[lane + 32 * it];
                    ulonglong2 cc = sz0[lane + 32 * it];
                    ulonglong2 d = dcur[i];
                    FFMA2(ar0, hA, a.x); FFMA2(ar0, hB, a.y);
                    FFMA2(ar1, hA, b.x); FFMA2(ar1, hB, b.y);
                    FFMA2(az0, hA, cc.x); FFMA2(az0, hB, cc.y);
                    FFMA2(az1, hA, d.x); FFMA2(az1, hB, d.y);
                    FFMA2(an0, hA, wn0[it].x); FFMA2(an0, hB, wn0[it].y);
                    FFMA2(an1, hA, wn1[it].x); FFMA2(an1, hB, wn1[it].y);
                }
            }
        }

        // ---- collapse pairs; fully interleaved 6-way butterfly reduce ----
        float2 pr0 = unpk(ar0), pr1 = unpk(ar1);
        float2 pz0 = unpk(az0), pz1 = unpk(az1);
        float2 pn0 = unpk(an0), pn1 = unpk(an1);
        float Ar0 = pr0.x + pr0.y, Ar1 = pr1.x + pr1.y;
        float Az0 = pz0.x + pz0.y, Az1 = pz1.x + pz1.y;
        float An0 = pn0.x + pn0.y, An1 = pn1.x + pn1.y;
        #pragma unroll
        for (int s = 16; s > 0; s >>= 1) {
            Ar0 += __shfl_xor_sync(0xffffffffu, Ar0, s);
            Ar1 += __shfl_xor_sync(0xffffffffu, Ar1, s);
            Az0 += __shfl_xor_sync(0xffffffffu, Az0, s);
            Az1 += __shfl_xor_sync(0xffffffffu, Az1, s);
            An0 += __shfl_xor_sync(0xffffffffu, An0, s);
            An1 += __shfl_xor_sync(0xffffffffu, An1, s);
        }
        float dr = (lane == 0) ? Ar0 : Ar1;
        float dz = (lane == 0) ? Az0 : Az1;
        float dn = (lane == 0) ? An0 : An1;
        float ar = fmaf(xt, ur, vr) + dr;
        float az = fmaf(xt, uz, vz) + dz;
        float r = __fdividef(1.0f, 1.0f + __expf(-ar));
        float z = __fdividef(1.0f, 1.0f + __expf(-az));
        float an = fmaf(xt, un, vn);
        float v = an + r * (dn + bh);
        float n = 1.0f - __fdividef(2.0f, 1.0f + __expf(2.0f * v));  // tanh(v)
        float hn = (1.0f - z) * n + z * hprev;
        hprev = hn;
        if (lane < 2 && jj < H) {
            #pragma unroll
            for (int rr = 0; rr < HREP; rr++)
                __stcg(&g_hrep[wb][rr][jj], hn);
            if (t == TSTEPS) out[jj] = hn;
        }
        __syncwarp();   // order lane1's stores before lane0's release

        // ---- publish: per-warp cta-release arrival; CTA winner does gpu atom;
        //      global laggard pre-releases its own next-step flag (skip poll) ----
        if (lane == 0) {
            unsigned old = atom_acqrel_add_s(cnt_sa, 1u);
            if (old == (unsigned)(NWARP * t - 1)) {
                unsigned gold = atom_acqrel_add_g(&g_ctr, 1u);
                if (gold == (unsigned)t * (unsigned)NCTA - 1u && t < TSTEPS)
                    st_rel_s(flag_sa, (unsigned)(t + 1));
            }
        }
    }
}

// ---------------- host launch ----------------
extern "C" void kernel_launch(void* const* d_in, const int* in_sizes, int n_in,
                              void* d_out, int out_size) {
    const float* x    = (const float*)d_in[0];
    const float* We   = (const float*)d_in[1];
    const float* be   = (const float*)d_in[2];
    const float* Wir  = (const float*)d_in[3];
    const float* bir  = (const float*)d_in[4];
    const float* Wiz  = (const float*)d_in[5];
    const float* biz  = (const float*)d_in[6];
    const float* Win  = (const float*)d_in[7];
    const float* bin_ = (const float*)d_in[8];
    const float* Whr  = (const float*)d_in[9];
    const float* Whz  = (const float*)d_in[10];
    const float* Whn  = (const float*)d_in[11];
    const float* bhn  = (const float*)d_in[12];
    float* out = (float*)d_out;

    cudaFuncSetAttribute(gru_kernel, cudaFuncAttributeMaxDynamicSharedMemorySize,
                         SMEM_BYTES);

    init_kernel<<<1, 1024>>>(x);
    transpose_kernel<<<dim3(H / 32, H / 32, 3), dim3(32, 8)>>>(Whr, Whz, Whn);
    prep_kernel<<<dim3(H / 128, H / 128), 128>>>(We, be, Wir, bir, Wiz, biz, Win, bin_);
    gru_kernel<<<NCTA, NTH, SMEM_BYTES>>>(bhn, out);
}

// round 14
// speedup vs baseline: 1.4229x; 1.1259x over previous
#include <cuda_runtime.h>
#include <cuda_bf16.h>
#include <math.h>

#define H      2048
#define TSTEPS 1024
#define NCTA   147
#define MAXC   14
#define JPAD   (NCTA * MAXC)      // 2058 padded columns
#define HPAD   2060
#define HREP   8                  // h replicas (consumers read cta&7)
#define HRS    2176               // replica stride in floats
#define NTH    224                // 7 warps, 2 columns each
#define NWARP  7

// smem layout (bytes): r cols bf16 [0,57344) ; z cols bf16 [57344,114688) ;
//                      hbuf fp32 [114688,122880) ; ctrl [122880,..)
#define SWZ_OFF   57344
#define HBUF_OFF  114688
#define CTRL_OFF  122880
#define SMEM_BYTES (122880 + 16)

typedef unsigned long long u64;

#define FFMA2(acc, a, b) \
    asm("fma.rn.f32x2 %0, %1, %2, %0;" : "+l"(acc) : "l"(a), "l"(b))

__device__ __forceinline__ float2 unpk(u64 v) {
    float2 r;
    asm("mov.b64 {%0, %1}, %2;" : "=f"(r.x), "=f"(r.y) : "l"(v));
    return r;
}
// two bf16 (packed u32) -> two f32 (packed u64); bf16->f32 is a 16-bit shift
__device__ __forceinline__ u64 bf2f(unsigned w) {
    unsigned lo = w << 16;
    unsigned hi = w & 0xFFFF0000u;
    u64 r;
    asm("mov.b64 %0, {%1, %2};" : "=l"(r) : "r"(lo), "r"(hi));
    return r;
}

// ---------------- persistent device state ----------------
__device__ __nv_bfloat16 g_Wbf[2][(size_t)JPAD * H]; // transposed bf16 Whr,Whz (col-major)
__device__ float    g_Wtn[(size_t)JPAD * H];         // transposed fp32 Whn
__device__ float    g_u[3][HPAD];
__device__ float    g_v[3][HPAD];
__device__ float    g_xs[TSTEPS];
__device__ float    g_hrep[2][HREP][HRS];            // replicated double-buffered h
__device__ unsigned g_ctr;

// ---------------- memory-order helpers ----------------
__device__ __forceinline__ unsigned ld_relax_g(const unsigned* p) {
    unsigned v;
    asm volatile("ld.relaxed.gpu.global.b32 %0, [%1];" : "=r"(v) : "l"(p) : "memory");
    return v;
}
__device__ __forceinline__ unsigned ld_acq_g(const unsigned* p) {
    unsigned v;
    asm volatile("ld.acquire.gpu.global.b32 %0, [%1];" : "=r"(v) : "l"(p) : "memory");
    return v;
}
__device__ __forceinline__ void red_rel_add_g(unsigned* p, unsigned v) {
    asm volatile("red.release.gpu.global.add.u32 [%0], %1;" :: "l"(p), "r"(v) : "memory");
}
__device__ __forceinline__ unsigned ld_acq_s(unsigned saddr) {
    unsigned v;
    asm volatile("ld.acquire.cta.shared.u32 %0, [%1];" : "=r"(v) : "r"(saddr) : "memory");
    return v;
}
__device__ __forceinline__ void st_rel_s(unsigned saddr, unsigned v) {
    asm volatile("st.release.cta.shared.u32 [%0], %1;" :: "r"(saddr), "r"(v) : "memory");
}
__device__ __forceinline__ unsigned atom_acqrel_add_s(unsigned saddr, unsigned v) {
    unsigned old;
    asm volatile("atom.acq_rel.cta.shared.add.u32 %0, [%1], %2;"
                 : "=r"(old) : "r"(saddr), "r"(v) : "memory");
    return old;
}

// ---------------- init ----------------
__global__ void init_kernel(const float* __restrict__ x) {
    int t = threadIdx.x;              // 0..1023
    int row = t >> 5;
    int c = t & 31;
    int oc = (row & 1) ? (31 - c) : c;
    g_xs[t] = x[(row << 5) + oc];
    for (int i = t; i < 2 * HREP * HRS; i += 1024)
        ((float*)g_hrep)[i] = 0.0f;
    for (int i = t; i < 3 * HPAD; i += 1024) {
        ((float*)g_u)[i] = 0.0f;
        ((float*)g_v)[i] = 0.0f;
    }
    if (t == 0) g_ctr = 0u;
}

// ---------------- transpose: Whr/Whz -> bf16 col-major; Whn -> fp32 col-major ----------------
__global__ void transpose_kernel(const float* __restrict__ Whr,
                                 const float* __restrict__ Whz,
                                 const float* __restrict__ Whn) {
    __shared__ float tile[32][33];
    const int g = blockIdx.z;
    const float* src = (g == 0) ? Whr : (g == 1) ? Whz : Whn;
    int k0 = blockIdx.x * 32;
    int j0 = blockIdx.y * 32;
    #pragma unroll
    for (int i = 0; i < 32; i += 8)
        tile[threadIdx.y + i][threadIdx.x] =
            src[(size_t)(k0 + threadIdx.y + i) * H + j0 + threadIdx.x];
    __syncthreads();
    if (g < 2) {
        __nv_bfloat16* dst = g_Wbf[g];
        #pragma unroll
        for (int i = 0; i < 32; i += 8)
            dst[(size_t)(j0 + threadIdx.y + i) * H + k0 + threadIdx.x] =
                __float2bfloat16(tile[threadIdx.x][threadIdx.y + i]);
    } else {
        #pragma unroll
        for (int i = 0; i < 32; i += 8)
            g_Wtn[(size_t)(j0 + threadIdx.y + i) * H + k0 + threadIdx.x] =
                tile[threadIdx.x][threadIdx.y + i];
    }
}

// ---------------- prep ----------------
__global__ void prep_kernel(const float* __restrict__ We, const float* __restrict__ be,
                            const float* __restrict__ Wir, const float* __restrict__ bir,
                            const float* __restrict__ Wiz, const float* __restrict__ biz,
                            const float* __restrict__ Win, const float* __restrict__ bin_) {
    int j  = blockIdx.x * 128 + threadIdx.x;
    int k0 = blockIdx.y * 128;
    float u0 = 0, v0 = 0, u1 = 0, v1 = 0, u2 = 0, v2 = 0;
    for (int k = k0; k < k0 + 128; k++) {
        float we = We[k];
        float b  = be[k];
        float w;
        w = Wir[(size_t)k * H + j]; u0 = fmaf(we, w, u0); v0 = fmaf(b, w, v0);
        w = Wiz[(size_t)k * H + j]; u1 = fmaf(we, w, u1); v1 = fmaf(b, w, v1);
        w = Win[(size_t)k * H + j]; u2 = fmaf(we, w, u2); v2 = fmaf(b, w, v2);
    }
    if (blockIdx.y == 0) { v0 += bir[j]; v1 += biz[j]; v2 += bin_[j]; }
    atomicAdd(&g_u[0][j], u0); atomicAdd(&g_v[0][j], v0);
    atomicAdd(&g_u[1][j], u1); atomicAdd(&g_v[1][j], v1);
    atomicAdd(&g_u[2][j], u2); atomicAdd(&g_v[2][j], v2);
}

// ---------------- persistent recurrent kernel ----------------
extern __shared__ char swb[];

__global__ void __launch_bounds__(NTH, 1) gru_kernel(const float* __restrict__ bhn,
                                                     float* __restrict__ out) {
    const int cta  = blockIdx.x;
    const int tid  = threadIdx.x;
    const int warp = tid >> 5;
    const int lane = tid & 31;
    const int cb   = cta * MAXC;
    const int rep  = cta & (HREP - 1);

    unsigned* ctrl = (unsigned*)(swb + CTRL_OFF);
    const unsigned flag_sa = (unsigned)__cvta_generic_to_shared(&ctrl[0]);
    const unsigned cnt_sa  = (unsigned)__cvta_generic_to_shared(&ctrl[1]);
    if (tid == 0) { ctrl[0] = 0u; ctrl[1] = 0u; }

    // ---- preload bf16 weights: all 14 r cols + 14 z cols into SMEM ----
    {
        const uint4* s0 = (const uint4*)(g_Wbf[0] + (size_t)cb * H);  // 57344 B
        const uint4* s1 = (const uint4*)(g_Wbf[1] + (size_t)cb * H);
        uint4* d0 = (uint4*)swb;
        uint4* d1 = (uint4*)(swb + SWZ_OFF);
        const int n16 = 14 * H * 2 / 16;   // 3584 uint4
        for (int i = tid; i < n16; i += NTH) { d0[i] = s0[i]; d1[i] = s1[i]; }
    }

    // ---- this warp's 2 columns ----
    const int c0 = 2 * warp, c1 = c0 + 1;
    const int j0 = cb + c0, j1 = cb + c1;

    // ---- Whn columns resident in registers as f32x2 pairs (8-iter indexing) ----
    u64 wn0p[32], wn1p[32];
    {
        const u64* p0 = (const u64*)(g_Wtn + (size_t)j0 * H);
        const u64* p1 = (const u64*)(g_Wtn + (size_t)j1 * H);
        #pragma unroll
        for (int i = 0; i < 8; i++)
            #pragma unroll
            for (int j = 0; j < 4; j++) {
                wn0p[4 * i + j] = p0[4 * (lane + 32 * i) + j];
                wn1p[4 * i + j] = p1[4 * (lane + 32 * i) + j];
            }
    }

    // ---- epilogue constants on lanes 0,1 ----
    const int jj = (lane == 0) ? j0 : j1;
    float ur = 0, vr = 0, uz = 0, vz = 0, un = 0, vn = 0, bh = 0, hprev = 0.0f;
    if (lane < 2) {
        int js = (jj < H) ? jj : (H - 1);
        ur = g_u[0][js]; vr = g_v[0][js];
        uz = g_u[1][js]; vz = g_v[1][js];
        un = g_u[2][js]; vn = g_v[2][js];
        bh = bhn[js];
    }

    const uint4* sr0 = (const uint4*)(swb + (size_t)c0 * H * 2);
    const uint4* sr1 = (const uint4*)(swb + (size_t)c1 * H * 2);
    const uint4* sz0 = (const uint4*)(swb + SWZ_OFF + (size_t)c0 * H * 2);
    const uint4* sz1 = (const uint4*)(swb + SWZ_OFF + (size_t)c1 * H * 2);
    const ulonglong2* hb2 = (const ulonglong2*)(swb + HBUF_OFF);
    const int rotA = (cta * 5) & 255;   // stagger line sweep across CTAs
    __syncthreads();   // smem weights + ctrl ready

    for (int t = 1; t <= TSTEPS; t++) {
        const int rb = (t - 1) & 1;
        const int wb = t & 1;

        float xt = __ldg(&g_xs[t - 1]);   // barrier-independent

        // ---- barrier: warp0 lane0 polls global counter, publishes smem flag ----
        if (warp == 0 && lane == 0) {
            if (t > 1) {
                const unsigned tgt = (unsigned)(t - 1) * NCTA;
                while (ld_relax_g(&g_ctr) < tgt) { }
                (void)ld_acq_g(&g_ctr);    // ordering edge (gpu scope)
            }
            st_rel_s(flag_sa, (unsigned)t);
        }
        while (ld_acq_s(flag_sa) < (unsigned)t) { }

        // ---- phase A: fill h[0:1024] -> smem (rotated sweep); phase B into regs ----
        const float4* hsrc = (const float4*)g_hrep[rb][rep];
        float4* hdst = (float4*)(swb + HBUF_OFF);
        {
            #pragma unroll
            for (int i = tid; i < 256; i += NTH) {
                int s = (i + rotA) & 255;
                hdst[s] = __ldcg(hsrc + s);
            }
        }
        float4 bA = __ldcg(hsrc + 256 + tid);                       // 256..479
        float4 bB;
        if (tid < 32) bB = __ldcg(hsrc + 480 + tid);                // 480..511
        __syncthreads();   // phase A visible

        // ---- dot iters 0..3 on phase A (phase-B LDGs in flight); 8 elems/lane/iter ----
        u64 ar0 = 0, ar1 = 0, az0 = 0, az1 = 0, an0 = 0, an1 = 0;
        #pragma unroll
        for (int i = 0; i < 4; i++) {
            int idx = lane + 32 * i;
            ulonglong2 hA2 = hb2[2 * idx];
            ulonglong2 hB2 = hb2[2 * idx + 1];
            uint4 wr0 = sr0[idx], wr1 = sr1[idx], wz0 = sz0[idx], wz1 = sz1[idx];
            FFMA2(ar0, hA2.x, bf2f(wr0.x)); FFMA2(ar0, hA2.y, bf2f(wr0.y));
            FFMA2(ar0, hB2.x, bf2f(wr0.z)); FFMA2(ar0, hB2.y, bf2f(wr0.w));
            FFMA2(ar1, hA2.x, bf2f(wr1.x)); FFMA2(ar1, hA2.y, bf2f(wr1.y));
            FFMA2(ar1, hB2.x, bf2f(wr1.z)); FFMA2(ar1, hB2.y, bf2f(wr1.w));
            FFMA2(az0, hA2.x, bf2f(wz0.x)); FFMA2(az0, hA2.y, bf2f(wz0.y));
            FFMA2(az0, hB2.x, bf2f(wz0.z)); FFMA2(az0, hB2.y, bf2f(wz0.w));
            FFMA2(az1, hA2.x, bf2f(wz1.x)); FFMA2(az1, hA2.y, bf2f(wz1.y));
            FFMA2(az1, hB2.x, bf2f(wz1.z)); FFMA2(az1, hB2.y, bf2f(wz1.w));
            FFMA2(an0, hA2.x, wn0p[4 * i]);     FFMA2(an0, hA2.y, wn0p[4 * i + 1]);
            FFMA2(an0, hB2.x, wn0p[4 * i + 2]); FFMA2(an0, hB2.y, wn0p[4 * i + 3]);
            FFMA2(an1, hA2.x, wn1p[4 * i]);     FFMA2(an1, hA2.y, wn1p[4 * i + 1]);
            FFMA2(an1, hB2.x, wn1p[4 * i + 2]); FFMA2(an1, hB2.y, wn1p[4 * i + 3]);
        }

        // ---- land phase B in smem ----
        hdst[256 + tid] = bA;
        if (tid < 32) hdst[480 + tid] = bB;
        __syncthreads();   // phase B visible

        // ---- dot iters 4..7 on phase B ----
        #pragma unroll
        for (int i = 4; i < 8; i++) {
            int idx = lane + 32 * i;
            ulonglong2 hA2 = hb2[2 * idx];
            ulonglong2 hB2 = hb2[2 * idx + 1];
            uint4 wr0 = sr0[idx], wr1 = sr1[idx], wz0 = sz0[idx], wz1 = sz1[idx];
            FFMA2(ar0, hA2.x, bf2f(wr0.x)); FFMA2(ar0, hA2.y, bf2f(wr0.y));
            FFMA2(ar0, hB2.x, bf2f(wr0.z)); FFMA2(ar0, hB2.y, bf2f(wr0.w));
            FFMA2(ar1, hA2.x, bf2f(wr1.x)); FFMA2(ar1, hA2.y, bf2f(wr1.y));
            FFMA2(ar1, hB2.x, bf2f(wr1.z)); FFMA2(ar1, hB2.y, bf2f(wr1.w));
            FFMA2(az0, hA2.x, bf2f(wz0.x)); FFMA2(az0, hA2.y, bf2f(wz0.y));
            FFMA2(az0, hB2.x, bf2f(wz0.z)); FFMA2(az0, hB2.y, bf2f(wz0.w));
            FFMA2(az1, hA2.x, bf2f(wz1.x)); FFMA2(az1, hA2.y, bf2f(wz1.y));
            FFMA2(az1, hB2.x, bf2f(wz1.z)); FFMA2(az1, hB2.y, bf2f(wz1.w));
            FFMA2(an0, hA2.x, wn0p[4 * i]);     FFMA2(an0, hA2.y, wn0p[4 * i + 1]);
            FFMA2(an0, hB2.x, wn0p[4 * i + 2]); FFMA2(an0, hB2.y, wn0p[4 * i + 3]);
            FFMA2(an1, hA2.x, wn1p[4 * i]);     FFMA2(an1, hA2.y, wn1p[4 * i + 1]);
            FFMA2(an1, hB2.x, wn1p[4 * i + 2]); FFMA2(an1, hB2.y, wn1p[4 * i + 3]);
        }

        // ---- collapse pairs; reduce r/z first so sigmoids start early ----
        float2 pr0 = unpk(ar0), pr1 = unpk(ar1);
        float2 pz0 = unpk(az0), pz1 = unpk(az1);
        float Ar0 = pr0.x + pr0.y, Ar1 = pr1.x + pr1.y;
        float Az0 = pz0.x + pz0.y, Az1 = pz1.x + pz1.y;
        #pragma unroll
        for (int s = 16; s > 0; s >>= 1) {
            Ar0 += __shfl_xor_sync(0xffffffffu, Ar0, s);
            Ar1 += __shfl_xor_sync(0xffffffffu, Ar1, s);
            Az0 += __shfl_xor_sync(0xffffffffu, Az0, s);
            Az1 += __shfl_xor_sync(0xffffffffu, Az1, s);
        }
        float dr = (lane == 0) ? Ar0 : Ar1;
        float dz = (lane == 0) ? Az0 : Az1;
        float ar = fmaf(xt, ur, vr) + dr;
        float az = fmaf(xt, uz, vz) + dz;
        float r = __fdividef(1.0f, 1.0f + __expf(-ar));
        float z = __fdividef(1.0f, 1.0f + __expf(-az));

        float2 pn0 = unpk(an0), pn1 = unpk(an1);
        float An0 = pn0.x + pn0.y, An1 = pn1.x + pn1.y;
        #pragma unroll
        for (int s = 16; s > 0; s >>= 1) {
            An0 += __shfl_xor_sync(0xffffffffu, An0, s);
            An1 += __shfl_xor_sync(0xffffffffu, An1, s);
        }
        float dn = (lane == 0) ? An0 : An1;
        float an = fmaf(xt, un, vn);
        float v = an + r * (dn + bh);
        float n = 1.0f - __fdividef(2.0f, 1.0f + __expf(2.0f * v));  // tanh(v)
        float hn = (1.0f - z) * n + z * hprev;
        hprev = hn;
        if (lane < 2 && jj < H) {
            #pragma unroll
            for (int rr = 0; rr < HREP; rr++)
                __stcg(&g_hrep[wb][rr][jj], hn);
            if (t == TSTEPS) out[jj] = hn;
        }
        __syncwarp();   // order lane1's stores before lane0's release

        // ---- publish: per-warp cta-release arrival; winner does gpu release ----
        if (lane == 0) {
            unsigned old = atom_acqrel_add_s(cnt_sa, 1u);
            if (old == (unsigned)(NWARP * t - 1)) red_rel_add_g(&g_ctr, 1u);
        }
    }
}

// ---------------- host launch ----------------
extern "C" void kernel_launch(void* const* d_in, const int* in_sizes, int n_in,
                              void* d_out, int out_size) {
    const float* x    = (const float*)d_in[0];
    const float* We   = (const float*)d_in[1];
    const float* be   = (const float*)d_in[2];
    const float* Wir  = (const float*)d_in[3];
    const float* bir  = (const float*)d_in[4];
    const float* Wiz  = (const float*)d_in[5];
    const float* biz  = (const float*)d_in[6];
    const float* Win  = (const float*)d_in[7];
    const float* bin_ = (const float*)d_in[8];
    const float* Whr  = (const float*)d_in[9];
    const float* Whz  = (const float*)d_in[10];
    const float* Whn  = (const float*)d_in[11];
    const float* bhn  = (const float*)d_in[12];
    float* out = (float*)d_out;

    cudaFuncSetAttribute(gru_kernel, cudaFuncAttributeMaxDynamicSharedMemorySize,
                         SMEM_BYTES);

    init_kernel<<<1, 1024>>>(x);
    transpose_kernel<<<dim3(H / 32, H / 32, 3), dim3(32, 8)>>>(Whr, Whz, Whn);
    prep_kernel<<<dim3(H / 128, H / 128), 128>>>(We, be, Wir, bir, Wiz, biz, Win, bin_);
    gru_kernel<<<NCTA, NTH, SMEM_BYTES>>>(bhn, out);
}

// round 17
// speedup vs baseline: 1.4318x; 1.0062x over previous
#include <cuda_runtime.h>
#include <cuda_bf16.h>
#include <math.h>

#define H      2048
#define TSTEPS 1024
#define NCTA   147
#define MAXC   14
#define JPAD   (NCTA * MAXC)      // 2058 padded columns
#define HPAD   2060
#define HREP   8                  // h replicas (consumers read cta&7)
#define HRS    2176               // replica stride in floats
#define NTH    224                // 7 warps, 2 columns each
#define NWARP  7

// smem layout (bytes): r cols bf16 [0,57344) ; z cols bf16 [57344,114688) ;
//                      hbuf fp32 [114688,122880) ; ctrl [122880,..)
#define SWZ_OFF   57344
#define HBUF_OFF  114688
#define CTRL_OFF  122880
#define SMEM_BYTES (122880 + 16)

typedef unsigned long long u64;

#define FFMA2(acc, a, b) \
    asm("fma.rn.f32x2 %0, %1, %2, %0;" : "+l"(acc) : "l"(a), "l"(b))

__device__ __forceinline__ float2 unpk(u64 v) {
    float2 r;
    asm("mov.b64 {%0, %1}, %2;" : "=f"(r.x), "=f"(r.y) : "l"(v));
    return r;
}
// two bf16 (packed u32) -> two f32 (packed u64); bf16->f32 is a 16-bit shift
__device__ __forceinline__ u64 bf2f(unsigned w) {
    unsigned lo = w << 16;
    unsigned hi = w & 0xFFFF0000u;
    u64 r;
    asm("mov.b64 %0, {%1, %2};" : "=l"(r) : "r"(lo), "r"(hi));
    return r;
}

// ---------------- persistent device state ----------------
__device__ __nv_bfloat16 g_Wbf[2][(size_t)JPAD * H]; // transposed bf16 Whr,Whz (col-major)
__device__ float    g_Wtn[(size_t)JPAD * H];         // transposed fp32 Whn
__device__ float    g_u[3][HPAD];
__device__ float    g_v[3][HPAD];
__device__ float    g_xs[TSTEPS];
__device__ float    g_hrep[2][HREP][HRS];            // replicated double-buffered h
__device__ unsigned g_ctr;

// ---------------- memory-order helpers ----------------
__device__ __forceinline__ unsigned ld_relax_g(const unsigned* p) {
    unsigned v;
    asm volatile("ld.relaxed.gpu.global.b32 %0, [%1];" : "=r"(v) : "l"(p) : "memory");
    return v;
}
__device__ __forceinline__ unsigned ld_acq_g(const unsigned* p) {
    unsigned v;
    asm volatile("ld.acquire.gpu.global.b32 %0, [%1];" : "=r"(v) : "l"(p) : "memory");
    return v;
}
__device__ __forceinline__ unsigned atom_acqrel_add_g(unsigned* p, unsigned v) {
    unsigned old;
    asm volatile("atom.acq_rel.gpu.global.add.u32 %0, [%1], %2;"
                 : "=r"(old) : "l"(p), "r"(v) : "memory");
    return old;
}
__device__ __forceinline__ unsigned ld_acq_s(unsigned saddr) {
    unsigned v;
    asm volatile("ld.acquire.cta.shared.u32 %0, [%1];" : "=r"(v) : "r"(saddr) : "memory");
    return v;
}
__device__ __forceinline__ void st_rel_s(unsigned saddr, unsigned v) {
    asm volatile("st.release.cta.shared.u32 [%0], %1;" :: "r"(saddr), "r"(v) : "memory");
}
__device__ __forceinline__ unsigned atom_acqrel_add_s(unsigned saddr, unsigned v) {
    unsigned old;
    asm volatile("atom.acq_rel.cta.shared.add.u32 %0, [%1], %2;"
                 : "=r"(old) : "r"(saddr), "r"(v) : "memory");
    return old;
}

// ---------------- init ----------------
__global__ void init_kernel(const float* __restrict__ x) {
    int t = threadIdx.x;              // 0..1023
    int row = t >> 5;
    int c = t & 31;
    int oc = (row & 1) ? (31 - c) : c;
    g_xs[t] = x[(row << 5) + oc];
    for (int i = t; i < 2 * HREP * HRS; i += 1024)
        ((float*)g_hrep)[i] = 0.0f;
    for (int i = t; i < 3 * HPAD; i += 1024) {
        ((float*)g_u)[i] = 0.0f;
        ((float*)g_v)[i] = 0.0f;
    }
    if (t == 0) g_ctr = 0u;
}

// ---------------- transpose: Whr/Whz -> bf16 col-major; Whn -> fp32 col-major ----------------
__global__ void transpose_kernel(const float* __restrict__ Whr,
                                 const float* __restrict__ Whz,
                                 const float* __restrict__ Whn) {
    __shared__ float tile[32][33];
    const int g = blockIdx.z;
    const float* src = (g == 0) ? Whr : (g == 1) ? Whz : Whn;
    int k0 = blockIdx.x * 32;
    int j0 = blockIdx.y * 32;
    #pragma unroll
    for (int i = 0; i < 32; i += 8)
        tile[threadIdx.y + i][threadIdx.x] =
            src[(size_t)(k0 + threadIdx.y + i) * H + j0 + threadIdx.x];
    __syncthreads();
    if (g < 2) {
        __nv_bfloat16* dst = g_Wbf[g];
        #pragma unroll
        for (int i = 0; i < 32; i += 8)
            dst[(size_t)(j0 + threadIdx.y + i) * H + k0 + threadIdx.x] =
                __float2bfloat16(tile[threadIdx.x][threadIdx.y + i]);
    } else {
        #pragma unroll
        for (int i = 0; i < 32; i += 8)
            g_Wtn[(size_t)(j0 + threadIdx.y + i) * H + k0 + threadIdx.x] =
                tile[threadIdx.x][threadIdx.y + i];
    }
}

// ---------------- prep ----------------
__global__ void prep_kernel(const float* __restrict__ We, const float* __restrict__ be,
                            const float* __restrict__ Wir, const float* __restrict__ bir,
                            const float* __restrict__ Wiz, const float* __restrict__ biz,
                            const float* __restrict__ Win, const float* __restrict__ bin_) {
    int j  = blockIdx.x * 128 + threadIdx.x;
    int k0 = blockIdx.y * 128;
    float u0 = 0, v0 = 0, u1 = 0, v1 = 0, u2 = 0, v2 = 0;
    for (int k = k0; k < k0 + 128; k++) {
        float we = We[k];
        float b  = be[k];
        float w;
        w = Wir[(size_t)k * H + j]; u0 = fmaf(we, w, u0); v0 = fmaf(b, w, v0);
        w = Wiz[(size_t)k * H + j]; u1 = fmaf(we, w, u1); v1 = fmaf(b, w, v1);
        w = Win[(size_t)k * H + j]; u2 = fmaf(we, w, u2); v2 = fmaf(b, w, v2);
    }
    if (blockIdx.y == 0) { v0 += bir[j]; v1 += biz[j]; v2 += bin_[j]; }
    atomicAdd(&g_u[0][j], u0); atomicAdd(&g_v[0][j], v0);
    atomicAdd(&g_u[1][j], u1); atomicAdd(&g_v[1][j], v1);
    atomicAdd(&g_u[2][j], u2); atomicAdd(&g_v[2][j], v2);
}

// ---------------- persistent recurrent kernel ----------------
extern __shared__ char swb[];

__global__ void __launch_bounds__(NTH, 1) gru_kernel(const float* __restrict__ bhn,
                                                     float* __restrict__ out) {
    const int cta  = blockIdx.x;
    const int tid  = threadIdx.x;
    const int warp = tid >> 5;
    const int lane = tid & 31;
    const int cb   = cta * MAXC;
    const int rep  = cta & (HREP - 1);

    unsigned* ctrl = (unsigned*)(swb + CTRL_OFF);
    const unsigned flag_sa = (unsigned)__cvta_generic_to_shared(&ctrl[0]);
    const unsigned cnt_sa  = (unsigned)__cvta_generic_to_shared(&ctrl[1]);
    if (tid == 0) { ctrl[0] = 0u; ctrl[1] = 0u; }

    // ---- preload bf16 weights: all 14 r cols + 14 z cols into SMEM ----
    {
        const uint4* s0 = (const uint4*)(g_Wbf[0] + (size_t)cb * H);  // 57344 B
        const uint4* s1 = (const uint4*)(g_Wbf[1] + (size_t)cb * H);
        uint4* d0 = (uint4*)swb;
        uint4* d1 = (uint4*)(swb + SWZ_OFF);
        const int n16 = 14 * H * 2 / 16;   // 3584 uint4
        for (int i = tid; i < n16; i += NTH) { d0[i] = s0[i]; d1[i] = s1[i]; }
    }

    // ---- this warp's 2 columns ----
    const int c0 = 2 * warp, c1 = c0 + 1;
    const int j0 = cb + c0, j1 = cb + c1;

    // ---- Whn columns resident in registers as f32x2 pairs (8-iter indexing) ----
    u64 wn0p[32], wn1p[32];
    {
        const u64* p0 = (const u64*)(g_Wtn + (size_t)j0 * H);
        const u64* p1 = (const u64*)(g_Wtn + (size_t)j1 * H);
        #pragma unroll
        for (int i = 0; i < 8; i++)
            #pragma unroll
            for (int j = 0; j < 4; j++) {
                wn0p[4 * i + j] = p0[4 * (lane + 32 * i) + j];
                wn1p[4 * i + j] = p1[4 * (lane + 32 * i) + j];
            }
    }

    // ---- epilogue constants on lanes 0,1 ----
    const int jj = (lane == 0) ? j0 : j1;
    float ur = 0, vr = 0, uz = 0, vz = 0, un = 0, vn = 0, bh = 0, hprev = 0.0f;
    if (lane < 2) {
        int js = (jj < H) ? jj : (H - 1);
        ur = g_u[0][js]; vr = g_v[0][js];
        uz = g_u[1][js]; vz = g_v[1][js];
        un = g_u[2][js]; vn = g_v[2][js];
        bh = bhn[js];
    }

    const uint4* sr0 = (const uint4*)(swb + (size_t)c0 * H * 2);
    const uint4* sr1 = (const uint4*)(swb + (size_t)c1 * H * 2);
    const uint4* sz0 = (const uint4*)(swb + SWZ_OFF + (size_t)c0 * H * 2);
    const uint4* sz1 = (const uint4*)(swb + SWZ_OFF + (size_t)c1 * H * 2);
    const ulonglong2* hb2 = (const ulonglong2*)(swb + HBUF_OFF);
    const int rotA = (cta * 5) & 255;   // stagger line sweep across CTAs
    __syncthreads();   // smem weights + ctrl ready

    for (int t = 1; t <= TSTEPS; t++) {
        const int rb = (t - 1) & 1;
        const int wb = t & 1;

        float xt = __ldg(&g_xs[t - 1]);   // barrier-independent

        // ---- barrier: warp0 lane0 polls global counter UNLESS this CTA was the
        //      global laggard last step (then flag_sa was pre-released) ----
        if (warp == 0 && lane == 0) {
            if (t > 1) {
                if (ld_acq_s(flag_sa) < (unsigned)t) {
                    const unsigned tgt = (unsigned)(t - 1) * NCTA;
                    while (ld_relax_g(&g_ctr) < tgt) { }
                    (void)ld_acq_g(&g_ctr);    // ordering edge (gpu scope)
                    st_rel_s(flag_sa, (unsigned)t);
                }
            } else {
                st_rel_s(flag_sa, 1u);
            }
        }
        while (ld_acq_s(flag_sa) < (unsigned)t) { }

        // ---- phase A: fill h[0:1024] -> smem (rotated sweep); phase B into regs ----
        const float4* hsrc = (const float4*)g_hrep[rb][rep];
        float4* hdst = (float4*)(swb + HBUF_OFF);
        {
            #pragma unroll
            for (int i = tid; i < 256; i += NTH) {
                int s = (i + rotA) & 255;
                hdst[s] = __ldcg(hsrc + s);
            }
        }
        float4 bA = __ldcg(hsrc + 256 + tid);                       // 256..479
        float4 bB;
        if (tid < 32) bB = __ldcg(hsrc + 480 + tid);                // 480..511
        __syncthreads();   // phase A visible

        // ---- dot iters 0..3 on phase A (phase-B LDGs in flight); 8 elems/lane/iter ----
        u64 ar0 = 0, ar1 = 0, az0 = 0, az1 = 0, an0 = 0, an1 = 0;
        #pragma unroll
        for (int i = 0; i < 4; i++) {
            int idx = lane + 32 * i;
            ulonglong2 hA2 = hb2[2 * idx];
            ulonglong2 hB2 = hb2[2 * idx + 1];
            uint4 wr0 = sr0[idx], wr1 = sr1[idx], wz0 = sz0[idx], wz1 = sz1[idx];
            FFMA2(ar0, hA2.x, bf2f(wr0.x)); FFMA2(ar0, hA2.y, bf2f(wr0.y));
            FFMA2(ar0, hB2.x, bf2f(wr0.z)); FFMA2(ar0, hB2.y, bf2f(wr0.w));
            FFMA2(ar1, hA2.x, bf2f(wr1.x)); FFMA2(ar1, hA2.y, bf2f(wr1.y));
            FFMA2(ar1, hB2.x, bf2f(wr1.z)); FFMA2(ar1, hB2.y, bf2f(wr1.w));
            FFMA2(az0, hA2.x, bf2f(wz0.x)); FFMA2(az0, hA2.y, bf2f(wz0.y));
            FFMA2(az0, hB2.x, bf2f(wz0.z)); FFMA2(az0, hB2.y, bf2f(wz0.w));
            FFMA2(az1, hA2.x, bf2f(wz1.x)); FFMA2(az1, hA2.y, bf2f(wz1.y));
            FFMA2(az1, hB2.x, bf2f(wz1.z)); FFMA2(az1, hB2.y, bf2f(wz1.w));
            FFMA2(an0, hA2.x, wn0p[4 * i]);     FFMA2(an0, hA2.y, wn0p[4 * i + 1]);
            FFMA2(an0, hB2.x, wn0p[4 * i + 2]); FFMA2(an0, hB2.y, wn0p[4 * i + 3]);
            FFMA2(an1, hA2.x, wn1p[4 * i]);     FFMA2(an1, hA2.y, wn1p[4 * i + 1]);
            FFMA2(an1, hB2.x, wn1p[4 * i + 2]); FFMA2(an1, hB2.y, wn1p[4 * i + 3]);
        }

        // ---- land phase B in smem ----
        hdst[256 + tid] = bA;
        if (tid < 32) hdst[480 + tid] = bB;
        __syncthreads();   // phase B visible

        // ---- dot iters 4..7 on phase B ----
        #pragma unroll
        for (int i = 4; i < 8; i++) {
            int idx = lane + 32 * i;
            ulonglong2 hA2 = hb2[2 * idx];
            ulonglong2 hB2 = hb2[2 * idx + 1];
            uint4 wr0 = sr0[idx], wr1 = sr1[idx], wz0 = sz0[idx], wz1 = sz1[idx];
            FFMA2(ar0, hA2.x, bf2f(wr0.x)); FFMA2(ar0, hA2.y, bf2f(wr0.y));
            FFMA2(ar0, hB2.x, bf2f(wr0.z)); FFMA2(ar0, hB2.y, bf2f(wr0.w));
            FFMA2(ar1, hA2.x, bf2f(wr1.x)); FFMA2(ar1, hA2.y, bf2f(wr1.y));
            FFMA2(ar1, hB2.x, bf2f(wr1.z)); FFMA2(ar1, hB2.y, bf2f(wr1.w));
            FFMA2(az0, hA2.x, bf2f(wz0.x)); FFMA2(az0, hA2.y, bf2f(wz0.y));
            FFMA2(az0, hB2.x, bf2f(wz0.z)); FFMA2(az0, hB2.y, bf2f(wz0.w));
            FFMA2(az1, hA2.x, bf2f(wz1.x)); FFMA2(az1, hA2.y, bf2f(wz1.y));
            FFMA2(az1, hB2.x, bf2f(wz1.z)); FFMA2(az1, hB2.y, bf2f(wz1.w));
            FFMA2(an0, hA2.x, wn0p[4 * i]);     FFMA2(an0, hA2.y, wn0p[4 * i + 1]);
            FFMA2(an0, hB2.x, wn0p[4 * i + 2]); FFMA2(an0, hB2.y, wn0p[4 * i + 3]);
            FFMA2(an1, hA2.x, wn1p[4 * i]);     FFMA2(an1, hA2.y, wn1p[4 * i + 1]);
            FFMA2(an1, hB2.x, wn1p[4 * i + 2]); FFMA2(an1, hB2.y, wn1p[4 * i + 3]);
        }

        // ---- collapse pairs; reduce r/z first so sigmoids start early ----
        float2 pr0 = unpk(ar0), pr1 = unpk(ar1);
        float2 pz0 = unpk(az0), pz1 = unpk(az1);
        float Ar0 = pr0.x + pr0.y, Ar1 = pr1.x + pr1.y;
        float Az0 = pz0.x + pz0.y, Az1 = pz1.x + pz1.y;
        #pragma unroll
        for (int s = 16; s > 0; s >>= 1) {
            Ar0 += __shfl_xor_sync(0xffffffffu, Ar0, s);
            Ar1 += __shfl_xor_sync(0xffffffffu, Ar1, s);
            Az0 += __shfl_xor_sync(0xffffffffu, Az0, s);
            Az1 += __shfl_xor_sync(0xffffffffu, Az1, s);
        }
        float dr = (lane == 0) ? Ar0 : Ar1;
        float dz = (lane == 0) ? Az0 : Az1;
        float ar = fmaf(xt, ur, vr) + dr;
        float az = fmaf(xt, uz, vz) + dz;
        float r = __fdividef(1.0f, 1.0f + __expf(-ar));
        float z = __fdividef(1.0f, 1.0f + __expf(-az));

        float2 pn0 = unpk(an0), pn1 = unpk(an1);
        float An0 = pn0.x + pn0.y, An1 = pn1.x + pn1.y;
        #pragma unroll
        for (int s = 16; s > 0; s >>= 1) {
            An0 += __shfl_xor_sync(0xffffffffu, An0, s);
            An1 += __shfl_xor_sync(0xffffffffu, An1, s);
        }
        float dn = (lane == 0) ? An0 : An1;
        float an = fmaf(xt, un, vn);
        float v = an + r * (dn + bh);
        float n = 1.0f - __fdividef(2.0f, 1.0f + __expf(2.0f * v));  // tanh(v)
        float hn = (1.0f - z) * n + z * hprev;
        hprev = hn;
        if (lane < 2 && jj < H) {
            #pragma unroll
            for (int rr = 0; rr < HREP; rr++)
                __stcg(&g_hrep[wb][rr][jj], hn);
            if (t == TSTEPS) out[jj] = hn;
        }
        __syncwarp();   // order lane1's stores before lane0's release

        // ---- publish: per-warp cta-release arrival; CTA winner does gpu atom;
        //      global laggard pre-releases its own next-step flag (skip poll) ----
        if (lane == 0) {
            unsigned old = atom_acqrel_add_s(cnt_sa, 1u);
            if (old == (unsigned)(NWARP * t - 1)) {
                unsigned gold = atom_acqrel_add_g(&g_ctr, 1u);
                if (gold == (unsigned)t * (unsigned)NCTA - 1u && t < TSTEPS)
                    st_rel_s(flag_sa, (unsigned)(t + 1));
            }
        }
    }
}

// ---------------- host launch ----------------
extern "C" void kernel_launch(void* const* d_in, const int* in_sizes, int n_in,
                              void* d_out, int out_size) {
    const float* x    = (const float*)d_in[0];
    const float* We   = (const float*)d_in[1];
    const float* be   = (const float*)d_in[2];
    const float* Wir  = (const float*)d_in[3];
    const float* bir  = (const float*)d_in[4];
    const float* Wiz  = (const float*)d_in[5];
    const float* biz  = (const float*)d_in[6];
    const float* Win  = (const float*)d_in[7];
    const float* bin_ = (const float*)d_in[8];
    const float* Whr  = (const float*)d_in[9];
    const float* Whz  = (const float*)d_in[10];
    const float* Whn  = (const float*)d_in[11];
    const float* bhn  = (const float*)d_in[12];
    float* out = (float*)d_out;

    cudaFuncSetAttribute(gru_kernel, cudaFuncAttributeMaxDynamicSharedMemorySize,
                         SMEM_BYTES);

    init_kernel<<<1, 1024>>>(x);
    transpose_kernel<<<dim3(H / 32, H / 32, 3), dim3(32, 8)>>>(Whr, Whz, Whn);
    prep_kernel<<<dim3(H / 128, H / 128), 128>>>(We, be, Wir, bir, Wiz, biz, Win, bin_);
    gru_kernel<<<NCTA, NTH, SMEM_BYTES>>>(bhn, out);
}